// round 5
// baseline (speedup 1.0000x reference)
#include <cuda_runtime.h>

#define NN 50000
#define EE 800000
#define GG 500
#define LL 3
#define NB1 ((NN + 1023) / 1024)

typedef unsigned long long u64;

__device__ __forceinline__ u64 ffma2(u64 a, u64 b, u64 c) {
    u64 d; asm("fma.rn.f32x2 %0,%1,%2,%3;" : "=l"(d) : "l"(a), "l"(b), "l"(c)); return d;
}
__device__ __forceinline__ u64 pk2(float lo, float hi) {
    u64 r; asm("mov.b64 %0,{%1,%2};" : "=l"(r) : "f"(lo), "f"(hi)); return r;
}
__device__ __forceinline__ float2 upk2(u64 v) {
    float2 f; asm("mov.b64 {%0,%1},%2;" : "=f"(f.x), "=f"(f.y) : "l"(v)); return f;
}

// ---------------- scratch (static device globals; no allocation) ----------------
__device__ int   g_is64;
__device__ int   g_degi[NN];
__device__ float g_degf[NN];
__device__ float g_dinv[NN];
__device__ int   g_ptr[NN + 1];
__device__ int   g_cnt[NN];
__device__ int   g_bsum[64];
__device__ int   g_boff[65];
__device__ int   g_csrc[EE];
__device__ float g_cw[EE];
__device__ float g_xc[NN * 128];   // [x | s] concat, row stride 128
__device__ float g_y[NN * 64];     // xc @ W1 (pre-aggregation GIN features)
__device__ float g_z[NN * 64];     // relu(agg(y)+b1) -> input of GIN gemm2
__device__ float g_hs[NN * 64];    // s @ gcnW
__device__ float g_x2[NN * 64];

// ---------------- index loading: int64 vs int32 auto-detect ----------------
__device__ __forceinline__ int ld_idx(const void* p, long i) {
    if (g_is64) return (int)((const long long*)p)[i];
    return ((const int*)p)[i];
}

__global__ void detect_k(const int* w) {
    if (blockIdx.x == 0 && threadIdx.x == 0) {
        int nz = 0;
#pragma unroll
        for (int j = 0; j < 8; j++)
            if (w[2 * j + 1] != 0) nz++;
        g_is64 = (nz == 0) ? 1 : 0;   // int64 little-endian => odd words are 0
    }
}

// ---------------- degree histogram ----------------
__global__ void hist_k(const void* ei) {
    int e = blockIdx.x * blockDim.x + threadIdx.x;
    if (e < EE) {
        int d = ld_idx(ei, (long)EE + e);
        atomicAdd(&g_degi[d], 1);
    }
}

__global__ void deg_k() {
    int i = blockIdx.x * blockDim.x + threadIdx.x;
    if (i < NN) {
        float d = (float)(g_degi[i] + 1);   // +1 self loop
        g_degf[i] = d;
        g_dinv[i] = rsqrtf(d);
    }
}

// ---------------- multi-block exclusive scan over degrees ----------------
__global__ void scan1_k() {
    __shared__ int sh[1024];
    int tid = threadIdx.x;
    int i = blockIdx.x * 1024 + tid;
    int v = (i < NN) ? g_degi[i] : 0;
    sh[tid] = v;
    __syncthreads();
    for (int off = 1; off < 1024; off <<= 1) {
        int t = (tid >= off) ? sh[tid - off] : 0;
        __syncthreads();
        sh[tid] += t;
        __syncthreads();
    }
    int incl = sh[tid];
    if (i < NN) g_ptr[i] = incl - v;
    if (tid == 1023) g_bsum[blockIdx.x] = incl;
}

__global__ void scan2_k() {
    if (threadIdx.x == 0) {
        int c = 0;
        for (int b = 0; b < NB1; b++) { g_boff[b] = c; c += g_bsum[b]; }
        g_boff[NB1] = c;
    }
}

__global__ void scan3_k() {
    int i = blockIdx.x * blockDim.x + threadIdx.x;
    if (i < NN) g_ptr[i] += g_boff[i >> 10];
    if (i == 0) g_ptr[NN] = g_boff[NB1];
}

// ---------------- CSR fill (src ids + gcn edge weights, grouped by dst) ----------------
__global__ void fill_k(const void* ei) {
    int e = blockIdx.x * blockDim.x + threadIdx.x;
    if (e < EE) {
        int sn = ld_idx(ei, e);
        int dn = ld_idx(ei, (long)EE + e);
        int pos = g_ptr[dn] + atomicAdd(&g_cnt[dn], 1);
        g_csrc[pos] = sn;
        g_cw[pos] = g_dinv[sn] * g_dinv[dn];
    }
}

// ---------------- fused GIN(y) + GCN(hs) aggregation ----------------
// warp per dst node; lanes 0-15 handle y (plain sum), lanes 16-31 handle hs
// (enorm-weighted sum). One 512B coalesced gather per edge covers both.
__global__ void agg_fused_k(const float* __restrict__ b1, const float* __restrict__ bg) {
    int nd = (blockIdx.x * blockDim.x + threadIdx.x) >> 5;
    if (nd >= NN) return;
    int lane = threadIdx.x & 31;
    int l4 = lane & 15;
    bool isY = lane < 16;
    const float4* base = isY ? (const float4*)g_y : (const float4*)g_hs;
    int b = g_ptr[nd], e = g_ptr[nd + 1];
    float4 a0 = make_float4(0.f, 0.f, 0.f, 0.f);
    float4 a1 = make_float4(0.f, 0.f, 0.f, 0.f);
    int i = b;
    for (; i + 1 < e; i += 2) {
        int s0 = g_csrc[i], s1 = g_csrc[i + 1];
        float w0 = isY ? 1.f : g_cw[i];
        float w1 = isY ? 1.f : g_cw[i + 1];
        float4 v0 = base[(long)s0 * 16 + l4];
        float4 v1 = base[(long)s1 * 16 + l4];
        a0.x = fmaf(w0, v0.x, a0.x); a0.y = fmaf(w0, v0.y, a0.y);
        a0.z = fmaf(w0, v0.z, a0.z); a0.w = fmaf(w0, v0.w, a0.w);
        a1.x = fmaf(w1, v1.x, a1.x); a1.y = fmaf(w1, v1.y, a1.y);
        a1.z = fmaf(w1, v1.z, a1.z); a1.w = fmaf(w1, v1.w, a1.w);
    }
    if (i < e) {
        int s0 = g_csrc[i];
        float w0 = isY ? 1.f : g_cw[i];
        float4 v0 = base[(long)s0 * 16 + l4];
        a0.x = fmaf(w0, v0.x, a0.x); a0.y = fmaf(w0, v0.y, a0.y);
        a0.z = fmaf(w0, v0.z, a0.z); a0.w = fmaf(w0, v0.w, a0.w);
    }
    a0.x += a1.x; a0.y += a1.y; a0.z += a1.z; a0.w += a1.w;
    // self term: weight 1 for GIN, 1/deg for GCN
    float ws = isY ? 1.f : (1.f / g_degf[nd]);
    float4 vs = base[(long)nd * 16 + l4];
    a0.x = fmaf(ws, vs.x, a0.x); a0.y = fmaf(ws, vs.y, a0.y);
    a0.z = fmaf(ws, vs.z, a0.z); a0.w = fmaf(ws, vs.w, a0.w);
    if (isY) {
        float4 r;
        r.x = fmaxf(a0.x + b1[4 * l4 + 0], 0.f);
        r.y = fmaxf(a0.y + b1[4 * l4 + 1], 0.f);
        r.z = fmaxf(a0.z + b1[4 * l4 + 2], 0.f);
        r.w = fmaxf(a0.w + b1[4 * l4 + 3], 0.f);
        ((float4*)g_z)[(long)nd * 16 + l4] = r;
    } else {
        float4 r;
        r.x = tanhf(a0.x + bg[4 * l4 + 0]);
        r.y = tanhf(a0.y + bg[4 * l4 + 1]);
        r.z = tanhf(a0.z + bg[4 * l4 + 2]);
        r.w = tanhf(a0.w + bg[4 * l4 + 3]);
        ((float4*)g_xc)[(long)nd * 32 + 16 + l4] = r;
    }
}

// ---------------- GEMM: out[n x 64] = act(in[n x K] @ W[K x 64] + b) ----------------
// f32x2 dual-issue path: weights pre-packed as k-pairs in smem (u64), input pairs
// read via natural LDS.64; accumulators hold {even-k, odd-k} partials.
// block = 128 rows x 64 cols, 256 threads, 8 rows x 4 cols per thread.
template <int K, int ACT>
__global__ void __launch_bounds__(256) gemm64_k(
        const float* __restrict__ in, int ldin,
        const float* __restrict__ Wm, const float* __restrict__ bias, int n,
        float* __restrict__ outA, int ldA) {
    constexpr int KC = (K < 32) ? K : 32;
    constexpr int KP2 = KC / 2;
    __shared__ float sIn[128][KC + 2];   // even stride -> every row 8B aligned
    __shared__ u64   sWp[KP2][66];       // [k-pair][col] packed {W[2k][c], W[2k+1][c]}

    int tid = threadIdx.x;
    int ct = tid & 15;    // cols 4*ct .. 4*ct+3
    int rt = tid >> 4;    // rows 8*rt .. 8*rt+7
    int rowBase = blockIdx.x * 128;

    u64 acc2[8][4];
#pragma unroll
    for (int r = 0; r < 8; r++)
#pragma unroll
        for (int c = 0; c < 4; c++) acc2[r][c] = 0ull;

    for (int kb = 0; kb < K; kb += KC) {
        for (int idx = tid; idx < 128 * (KC / 4); idx += 256) {
            int r = idx / (KC / 4), q = idx - r * (KC / 4);
            int gr = rowBase + r;
            float4 v = (gr < n) ? *(const float4*)&in[(long)gr * ldin + kb + 4 * q]
                                : make_float4(0.f, 0.f, 0.f, 0.f);
            *(float2*)&sIn[r][4 * q]     = make_float2(v.x, v.y);
            *(float2*)&sIn[r][4 * q + 2] = make_float2(v.z, v.w);
        }
        for (int idx = tid; idx < KP2 * 64; idx += 256) {
            int kk = idx >> 6, c = idx & 63;
            sWp[kk][c] = pk2(Wm[(long)(kb + 2 * kk) * 64 + c],
                             Wm[(long)(kb + 2 * kk + 1) * 64 + c]);
        }
        __syncthreads();
#pragma unroll
        for (int kk = 0; kk < KP2; kk++) {
            u64 a2[8];
#pragma unroll
            for (int j = 0; j < 8; j++)
                a2[j] = *(const u64*)&sIn[8 * rt + j][2 * kk];
            u64 w0 = sWp[kk][4 * ct + 0];
            u64 w1 = sWp[kk][4 * ct + 1];
            u64 w2 = sWp[kk][4 * ct + 2];
            u64 w3 = sWp[kk][4 * ct + 3];
#pragma unroll
            for (int j = 0; j < 8; j++) {
                acc2[j][0] = ffma2(a2[j], w0, acc2[j][0]);
                acc2[j][1] = ffma2(a2[j], w1, acc2[j][1]);
                acc2[j][2] = ffma2(a2[j], w2, acc2[j][2]);
                acc2[j][3] = ffma2(a2[j], w3, acc2[j][3]);
            }
        }
        __syncthreads();
    }

    float bs[4];
#pragma unroll
    for (int c = 0; c < 4; c++) bs[c] = bias ? bias[4 * ct + c] : 0.f;
#pragma unroll
    for (int r = 0; r < 8; r++) {
        int gr = rowBase + 8 * rt + r;
        if (gr < n) {
#pragma unroll
            for (int c = 0; c < 4; c++) {
                float2 p = upk2(acc2[r][c]);
                float v = p.x + p.y + bs[c];
                if (ACT) v = fmaxf(v, 0.f);
                outA[(long)gr * ldA + 4 * ct + c] = v;
            }
        }
    }
}

// ---------------- fused global add pool + post + readout + log_softmax ----------------
__global__ void poolhead_k(const void* __restrict__ batch,
                           const float* __restrict__ postW, const float* __restrict__ postb,
                           const float* __restrict__ roW, const float* __restrict__ rob,
                           float* __restrict__ out) {
    int g = blockIdx.x;
    int t = threadIdx.x;   // 64 threads, one column each
    int lo = 0, hi = NN;
    while (lo < hi) { int mid = (lo + hi) >> 1; if (ld_idx(batch, mid) < g) lo = mid + 1; else hi = mid; }
    int beg = lo;
    hi = NN;
    while (lo < hi) { int mid = (lo + hi) >> 1; if (ld_idx(batch, mid) < g + 1) lo = mid + 1; else hi = mid; }
    int end = lo;

    float acc = 0.f;
    for (int nd = beg; nd < end; nd++) acc += g_x2[(long)nd * 64 + t];

    __shared__ float sg[64], sh1[64], sl[10];
    sg[t] = acc;
    __syncthreads();
    float a = postb[t];
#pragma unroll
    for (int k = 0; k < 64; k++) a = fmaf(sg[k], postW[k * 64 + t], a);
    sh1[t] = fmaxf(a, 0.f);
    __syncthreads();
    if (t < 10) {
        float r = rob[t];
#pragma unroll
        for (int k = 0; k < 64; k++) r = fmaf(sh1[k], roW[k * 10 + t], r);
        sl[t] = r;
    }
    __syncthreads();
    if (t == 0) {
        float m = sl[0];
#pragma unroll
        for (int c = 1; c < 10; c++) m = fmaxf(m, sl[c]);
        float sum = 0.f;
#pragma unroll
        for (int c = 0; c < 10; c++) sum += expf(sl[c] - m);
        float lse = m + logf(sum);
#pragma unroll
        for (int c = 0; c < 10; c++) out[g * 10 + c] = sl[c] - lse;
    }
}

// ---------------- launch ----------------
extern "C" void kernel_launch(void* const* d_in, const int* in_sizes, int n_in,
                              void* d_out, int out_size) {
    const float* x_in  = (const float*)d_in[0];
    const float* s_in  = (const float*)d_in[1];
    const void*  ei    = d_in[2];
    const void*  batch = d_in[3];
    const float* preW  = (const float*)d_in[4];
    const float* preb  = (const float*)d_in[5];
    const float* embW  = (const float*)d_in[6];
    const float* embb  = (const float*)d_in[7];
    const float* ginW1 = (const float*)d_in[8];
    const float* ginb1 = (const float*)d_in[9];
    const float* ginW2 = (const float*)d_in[10];
    const float* ginb2 = (const float*)d_in[11];
    const float* gcnW  = (const float*)d_in[12];
    const float* gcnb  = (const float*)d_in[13];
    const float* whpW  = (const float*)d_in[14];
    const float* whpb  = (const float*)d_in[15];
    const float* postW = (const float*)d_in[16];
    const float* postb = (const float*)d_in[17];
    const float* roW   = (const float*)d_in[18];
    const float* rob   = (const float*)d_in[19];
    float* out = (float*)d_out;

    void *p_degi, *p_cnt, *p_xc, *p_y, *p_z, *p_hs, *p_x2;
    cudaGetSymbolAddress(&p_degi, g_degi);
    cudaGetSymbolAddress(&p_cnt, g_cnt);
    cudaGetSymbolAddress(&p_xc, g_xc);
    cudaGetSymbolAddress(&p_y, g_y);
    cudaGetSymbolAddress(&p_z, g_z);
    cudaGetSymbolAddress(&p_hs, g_hs);
    cudaGetSymbolAddress(&p_x2, g_x2);
    float* xc = (float*)p_xc;
    float* ybuf = (float*)p_y;
    float* zbuf = (float*)p_z;
    float* hs = (float*)p_hs;
    float* x2 = (float*)p_x2;

    cudaMemsetAsync(p_degi, 0, NN * sizeof(int), 0);
    cudaMemsetAsync(p_cnt, 0, NN * sizeof(int), 0);

    detect_k<<<1, 32>>>((const int*)ei);

    const int TB = 256;
    const int gridE = (EE + TB - 1) / TB;
    const int gridN = (NN + TB - 1) / TB;
    const int gridW = (NN * 32 + TB - 1) / TB;
    const int gridM = (NN + 127) / 128;

    hist_k<<<gridE, TB>>>(ei);
    deg_k<<<gridN, TB>>>();
    scan1_k<<<NB1, 1024>>>();
    scan2_k<<<1, 32>>>();
    scan3_k<<<gridN, TB>>>();
    fill_k<<<gridE, TB>>>(ei);

    // pre: x -> xc[:, :64];  emb: s -> xc[:, 64:]
    gemm64_k<128, 0><<<gridM, TB>>>(x_in, 128, preW, preb, NN, xc, 128);
    gemm64_k<16, 0><<<gridM, TB>>>(s_in, 16, embW, embb, NN, xc + 64, 128);

    for (int i = 0; i < LL; i++) {
        // y = xc @ W1 (bias deferred to agg); hs = s @ gcnW (s = xc[:,64:])
        gemm64_k<128, 0><<<gridM, TB>>>(xc, 128, ginW1 + (long)i * 128 * 64, nullptr,
                                        NN, ybuf, 64);
        gemm64_k<64, 0><<<gridM, TB>>>(xc + 64, 128, gcnW + (long)i * 64 * 64, nullptr,
                                       NN, hs, 64);
        // z = relu(y_self + sum y_src + b1); s' = tanh(sum w*hs + hs_self/deg + bg)
        agg_fused_k<<<gridW, TB>>>(ginb1 + i * 64, gcnb + i * 64);
        // x = relu(z @ W2 + b2) -> xc[:, :64]
        gemm64_k<64, 1><<<gridM, TB>>>(zbuf, 64, ginW2 + (long)i * 64 * 64, ginb2 + i * 64,
                                       NN, xc, 128);
    }

    gemm64_k<128, 0><<<gridM, TB>>>(xc, 128, whpW, whpb, NN, x2, 64);
    poolhead_k<<<GG, 64>>>(batch, postW, postb, roW, rob, out);
}

// round 7
// speedup vs baseline: 1.2476x; 1.2476x over previous
#include <cuda_runtime.h>

#define NN 50000
#define EE 800000
#define GG 500
#define LL 3
#define NB1 ((NN + 1023) / 1024)

// ---------------- scratch (static device globals; no allocation) ----------------
__device__ int   g_is64;
__device__ int   g_degi[NN];
__device__ float g_degf[NN];
__device__ float g_dinv[NN];
__device__ int   g_ptr[NN + 1];
__device__ int   g_cnt[NN];
__device__ int   g_bsum[64];
__device__ int   g_boff[65];
__device__ int   g_csrc[EE];
__device__ float g_cw[EE];
__device__ float g_xc[NN * 128];   // [x | s] concat, row stride 128
__device__ float g_y[NN * 64];     // xc @ W1 (pre-aggregation GIN features)
__device__ float g_z[NN * 64];     // relu(agg(y)+b1) -> input of GIN gemm2
__device__ float g_hs[NN * 64];    // s @ gcnW
__device__ float g_x2[NN * 64];

// ---------------- index loading: int64 vs int32 auto-detect ----------------
__device__ __forceinline__ int ld_idx(const void* p, long i) {
    if (g_is64) return (int)((const long long*)p)[i];
    return ((const int*)p)[i];
}

__global__ void detect_k(const int* w) {
    if (blockIdx.x == 0 && threadIdx.x == 0) {
        int nz = 0;
#pragma unroll
        for (int j = 0; j < 8; j++)
            if (w[2 * j + 1] != 0) nz++;
        g_is64 = (nz == 0) ? 1 : 0;   // int64 little-endian => odd words are 0
    }
}

// ---------------- degree histogram ----------------
__global__ void hist_k(const void* ei) {
    int e = blockIdx.x * blockDim.x + threadIdx.x;
    if (e < EE) {
        int d = ld_idx(ei, (long)EE + e);
        atomicAdd(&g_degi[d], 1);
    }
}

__global__ void deg_k() {
    int i = blockIdx.x * blockDim.x + threadIdx.x;
    if (i < NN) {
        float d = (float)(g_degi[i] + 1);   // +1 self loop
        g_degf[i] = d;
        g_dinv[i] = rsqrtf(d);
    }
}

// ---------------- multi-block exclusive scan over degrees ----------------
__global__ void scan1_k() {
    __shared__ int sh[1024];
    int tid = threadIdx.x;
    int i = blockIdx.x * 1024 + tid;
    int v = (i < NN) ? g_degi[i] : 0;
    sh[tid] = v;
    __syncthreads();
    for (int off = 1; off < 1024; off <<= 1) {
        int t = (tid >= off) ? sh[tid - off] : 0;
        __syncthreads();
        sh[tid] += t;
        __syncthreads();
    }
    int incl = sh[tid];
    if (i < NN) g_ptr[i] = incl - v;
    if (tid == 1023) g_bsum[blockIdx.x] = incl;
}

__global__ void scan2_k() {
    if (threadIdx.x == 0) {
        int c = 0;
        for (int b = 0; b < NB1; b++) { g_boff[b] = c; c += g_bsum[b]; }
        g_boff[NB1] = c;
    }
}

__global__ void scan3_k() {
    int i = blockIdx.x * blockDim.x + threadIdx.x;
    if (i < NN) g_ptr[i] += g_boff[i >> 10];
    if (i == 0) g_ptr[NN] = g_boff[NB1];
}

// ---------------- CSR fill (src ids + gcn edge weights, grouped by dst) ----------------
__global__ void fill_k(const void* ei) {
    int e = blockIdx.x * blockDim.x + threadIdx.x;
    if (e < EE) {
        int sn = ld_idx(ei, e);
        int dn = ld_idx(ei, (long)EE + e);
        int pos = g_ptr[dn] + atomicAdd(&g_cnt[dn], 1);
        g_csrc[pos] = sn;
        g_cw[pos] = g_dinv[sn] * g_dinv[dn];
    }
}

// ---------------- fused GIN(y) + GCN(hs) aggregation ----------------
// warp per dst node; lanes 0-15 handle y (plain sum), lanes 16-31 handle hs
// (enorm-weighted sum). One coalesced 2x256B gather per edge covers both.
__global__ void agg_fused_k(const float* __restrict__ b1, const float* __restrict__ bg) {
    int nd = (blockIdx.x * blockDim.x + threadIdx.x) >> 5;
    if (nd >= NN) return;
    int lane = threadIdx.x & 31;
    int l4 = lane & 15;
    bool isY = lane < 16;
    const float4* base = isY ? (const float4*)g_y : (const float4*)g_hs;
    int b = g_ptr[nd], e = g_ptr[nd + 1];
    float4 a0 = make_float4(0.f, 0.f, 0.f, 0.f);
    float4 a1 = make_float4(0.f, 0.f, 0.f, 0.f);
    int i = b;
    for (; i + 1 < e; i += 2) {
        int s0 = g_csrc[i], s1 = g_csrc[i + 1];
        float w0 = isY ? 1.f : g_cw[i];
        float w1 = isY ? 1.f : g_cw[i + 1];
        float4 v0 = base[(long)s0 * 16 + l4];
        float4 v1 = base[(long)s1 * 16 + l4];
        a0.x = fmaf(w0, v0.x, a0.x); a0.y = fmaf(w0, v0.y, a0.y);
        a0.z = fmaf(w0, v0.z, a0.z); a0.w = fmaf(w0, v0.w, a0.w);
        a1.x = fmaf(w1, v1.x, a1.x); a1.y = fmaf(w1, v1.y, a1.y);
        a1.z = fmaf(w1, v1.z, a1.z); a1.w = fmaf(w1, v1.w, a1.w);
    }
    if (i < e) {
        int s0 = g_csrc[i];
        float w0 = isY ? 1.f : g_cw[i];
        float4 v0 = base[(long)s0 * 16 + l4];
        a0.x = fmaf(w0, v0.x, a0.x); a0.y = fmaf(w0, v0.y, a0.y);
        a0.z = fmaf(w0, v0.z, a0.z); a0.w = fmaf(w0, v0.w, a0.w);
    }
    a0.x += a1.x; a0.y += a1.y; a0.z += a1.z; a0.w += a1.w;
    // self term: weight 1 for GIN, 1/deg for GCN
    float ws = isY ? 1.f : (1.f / g_degf[nd]);
    float4 vs = base[(long)nd * 16 + l4];
    a0.x = fmaf(ws, vs.x, a0.x); a0.y = fmaf(ws, vs.y, a0.y);
    a0.z = fmaf(ws, vs.z, a0.z); a0.w = fmaf(ws, vs.w, a0.w);
    if (isY) {
        float4 r;
        r.x = fmaxf(a0.x + b1[4 * l4 + 0], 0.f);
        r.y = fmaxf(a0.y + b1[4 * l4 + 1], 0.f);
        r.z = fmaxf(a0.z + b1[4 * l4 + 2], 0.f);
        r.w = fmaxf(a0.w + b1[4 * l4 + 3], 0.f);
        ((float4*)g_z)[(long)nd * 16 + l4] = r;
    } else {
        float4 r;
        r.x = tanhf(a0.x + bg[4 * l4 + 0]);
        r.y = tanhf(a0.y + bg[4 * l4 + 1]);
        r.z = tanhf(a0.z + bg[4 * l4 + 2]);
        r.w = tanhf(a0.w + bg[4 * l4 + 3]);
        ((float4*)g_xc)[(long)nd * 32 + 16 + l4] = r;
    }
}

// ---------------- GEMM: out[n x 64] = act(in[n x K] @ W[K x 64] + b) ----------------
// Scalar-FFMA path (proven R4): block = 128 rows x 64 cols, 256 threads,
// 8x4 register tile, KC<=32 k-chunks, conflict-free float4 weight reads.
template <int K, int ACT>
__global__ void __launch_bounds__(256) gemm64_k(
        const float* __restrict__ in, int ldin,
        const float* __restrict__ Wm, const float* __restrict__ bias, int n,
        float* __restrict__ outA, int ldA) {
    constexpr int KC = (K < 32) ? K : 32;
    __shared__ float sIn[128][KC + 1];
    __shared__ float sW[KC][68];   // row stride 68 floats => 16B-aligned float4 reads

    int tid = threadIdx.x;
    int ct = tid & 15;    // col tile: cols 4*ct .. 4*ct+3
    int rt = tid >> 4;    // row tile: rows 8*rt .. 8*rt+7
    int rowBase = blockIdx.x * 128;

    float acc[8][4];
    float bseed[4];
#pragma unroll
    for (int c = 0; c < 4; c++) bseed[c] = bias ? bias[4 * ct + c] : 0.f;
#pragma unroll
    for (int r = 0; r < 8; r++)
#pragma unroll
        for (int c = 0; c < 4; c++) acc[r][c] = bseed[c];

    for (int kb = 0; kb < K; kb += KC) {
        for (int idx = tid; idx < 128 * KC; idx += 256) {
            int r = idx / KC, k = idx - r * KC;
            int gr = rowBase + r;
            sIn[r][k] = (gr < n) ? in[(long)gr * ldin + kb + k] : 0.f;
        }
        for (int idx = tid; idx < KC * 64; idx += 256) {
            int k = idx >> 6, c = idx & 63;
            sW[k][c] = Wm[(long)(kb + k) * 64 + c];
        }
        __syncthreads();
#pragma unroll 8
        for (int k = 0; k < KC; k++) {
            float4 w = *(const float4*)&sW[k][4 * ct];
            float a[8];
#pragma unroll
            for (int j = 0; j < 8; j++) a[j] = sIn[8 * rt + j][k];
#pragma unroll
            for (int j = 0; j < 8; j++) {
                acc[j][0] = fmaf(a[j], w.x, acc[j][0]);
                acc[j][1] = fmaf(a[j], w.y, acc[j][1]);
                acc[j][2] = fmaf(a[j], w.z, acc[j][2]);
                acc[j][3] = fmaf(a[j], w.w, acc[j][3]);
            }
        }
        __syncthreads();
    }

#pragma unroll
    for (int r = 0; r < 8; r++) {
        int gr = rowBase + 8 * rt + r;
        if (gr < n) {
#pragma unroll
            for (int c = 0; c < 4; c++) {
                float v = acc[r][c];
                if (ACT) v = fmaxf(v, 0.f);
                outA[(long)gr * ldA + 4 * ct + c] = v;
            }
        }
    }
}

// ---------------- fused global add pool + post + readout + log_softmax ----------------
__global__ void poolhead_k(const void* __restrict__ batch,
                           const float* __restrict__ postW, const float* __restrict__ postb,
                           const float* __restrict__ roW, const float* __restrict__ rob,
                           float* __restrict__ out) {
    int g = blockIdx.x;
    int t = threadIdx.x;   // 64 threads, one column each
    int lo = 0, hi = NN;
    while (lo < hi) { int mid = (lo + hi) >> 1; if (ld_idx(batch, mid) < g) lo = mid + 1; else hi = mid; }
    int beg = lo;
    hi = NN;
    while (lo < hi) { int mid = (lo + hi) >> 1; if (ld_idx(batch, mid) < g + 1) lo = mid + 1; else hi = mid; }
    int end = lo;

    float acc = 0.f;
    for (int nd = beg; nd < end; nd++) acc += g_x2[(long)nd * 64 + t];

    __shared__ float sg[64], sh1[64], sl[10];
    sg[t] = acc;
    __syncthreads();
    float a = postb[t];
#pragma unroll
    for (int k = 0; k < 64; k++) a = fmaf(sg[k], postW[k * 64 + t], a);
    sh1[t] = fmaxf(a, 0.f);
    __syncthreads();
    if (t < 10) {
        float r = rob[t];
#pragma unroll
        for (int k = 0; k < 64; k++) r = fmaf(sh1[k], roW[k * 10 + t], r);
        sl[t] = r;
    }
    __syncthreads();
    if (t == 0) {
        float m = sl[0];
#pragma unroll
        for (int c = 1; c < 10; c++) m = fmaxf(m, sl[c]);
        float sum = 0.f;
#pragma unroll
        for (int c = 0; c < 10; c++) sum += expf(sl[c] - m);
        float lse = m + logf(sum);
#pragma unroll
        for (int c = 0; c < 10; c++) out[g * 10 + c] = sl[c] - lse;
    }
}

// ---------------- launch ----------------
extern "C" void kernel_launch(void* const* d_in, const int* in_sizes, int n_in,
                              void* d_out, int out_size) {
    const float* x_in  = (const float*)d_in[0];
    const float* s_in  = (const float*)d_in[1];
    const void*  ei    = d_in[2];
    const void*  batch = d_in[3];
    const float* preW  = (const float*)d_in[4];
    const float* preb  = (const float*)d_in[5];
    const float* embW  = (const float*)d_in[6];
    const float* embb  = (const float*)d_in[7];
    const float* ginW1 = (const float*)d_in[8];
    const float* ginb1 = (const float*)d_in[9];
    const float* ginW2 = (const float*)d_in[10];
    const float* ginb2 = (const float*)d_in[11];
    const float* gcnW  = (const float*)d_in[12];
    const float* gcnb  = (const float*)d_in[13];
    const float* whpW  = (const float*)d_in[14];
    const float* whpb  = (const float*)d_in[15];
    const float* postW = (const float*)d_in[16];
    const float* postb = (const float*)d_in[17];
    const float* roW   = (const float*)d_in[18];
    const float* rob   = (const float*)d_in[19];
    float* out = (float*)d_out;

    void *p_degi, *p_cnt, *p_xc, *p_y, *p_z, *p_hs, *p_x2;
    cudaGetSymbolAddress(&p_degi, g_degi);
    cudaGetSymbolAddress(&p_cnt, g_cnt);
    cudaGetSymbolAddress(&p_xc, g_xc);
    cudaGetSymbolAddress(&p_y, g_y);
    cudaGetSymbolAddress(&p_z, g_z);
    cudaGetSymbolAddress(&p_hs, g_hs);
    cudaGetSymbolAddress(&p_x2, g_x2);
    float* xc = (float*)p_xc;
    float* ybuf = (float*)p_y;
    float* zbuf = (float*)p_z;
    float* hs = (float*)p_hs;
    float* x2 = (float*)p_x2;

    cudaMemsetAsync(p_degi, 0, NN * sizeof(int), 0);
    cudaMemsetAsync(p_cnt, 0, NN * sizeof(int), 0);

    detect_k<<<1, 32>>>((const int*)ei);

    const int TB = 256;
    const int gridE = (EE + TB - 1) / TB;
    const int gridN = (NN + TB - 1) / TB;
    const int gridW = (NN * 32 + TB - 1) / TB;
    const int gridM = (NN + 127) / 128;

    hist_k<<<gridE, TB>>>(ei);
    deg_k<<<gridN, TB>>>();
    scan1_k<<<NB1, 1024>>>();
    scan2_k<<<1, 32>>>();
    scan3_k<<<gridN, TB>>>();
    fill_k<<<gridE, TB>>>(ei);

    // pre: x -> xc[:, :64];  emb: s -> xc[:, 64:]
    gemm64_k<128, 0><<<gridM, TB>>>(x_in, 128, preW, preb, NN, xc, 128);
    gemm64_k<16, 0><<<gridM, TB>>>(s_in, 16, embW, embb, NN, xc + 64, 128);

    for (int i = 0; i < LL; i++) {
        // y = xc @ W1 (bias deferred to agg); hs = s @ gcnW (s = xc[:,64:])
        gemm64_k<128, 0><<<gridM, TB>>>(xc, 128, ginW1 + (long)i * 128 * 64, nullptr,
                                        NN, ybuf, 64);
        gemm64_k<64, 0><<<gridM, TB>>>(xc + 64, 128, gcnW + (long)i * 64 * 64, nullptr,
                                       NN, hs, 64);
        // z = relu(y_self + sum y_src + b1); s' = tanh(sum w*hs + hs_self/deg + bg)
        agg_fused_k<<<gridW, TB>>>(ginb1 + i * 64, gcnb + i * 64);
        // x = relu(z @ W2 + b2) -> xc[:, :64]
        gemm64_k<64, 1><<<gridM, TB>>>(zbuf, 64, ginW2 + (long)i * 64 * 64, ginb2 + i * 64,
                                       NN, xc, 128);
    }

    gemm64_k<128, 0><<<gridM, TB>>>(xc, 128, whpW, whpb, NN, x2, 64);
    poolhead_k<<<GG, 64>>>(batch, postW, postb, roW, rob, out);
}